// round 10
// baseline (speedup 1.0000x reference)
#include <cuda_runtime.h>
#include <cstdint>
#include <cstddef>

// Problem constants (fixed by setup_inputs)
#define N_ 8
#define C_ 256
#define H_ 64
#define W_ 64
#define A_ 9
#define BS_ 8
#define F_ 8
#define K_ 64
#define M_ (A_*N_*K_)   // 4608

// Scratch (static device globals; no runtime allocation)
__device__ float g_reg[N_*A_*F_*F_];           // 4608 conv outputs
__device__ float g_roisb[(size_t)M_*C_];       // sampled rois_feature_b
__device__ float g_tmp[(size_t)M_*C_];         // intermediate rois output

// ---------------------------------------------------------------------------
// Kernel 1: zero the conv accumulator (atomics accumulate into it each launch)
// ---------------------------------------------------------------------------
__global__ void zero_reg_kernel() {
    int i = blockIdx.x * blockDim.x + threadIdx.x;
    if (i < N_*A_*F_*F_) g_reg[i] = 0.f;
}

// ---------------------------------------------------------------------------
// Kernel 2: stride-8 8x8 "VALID" conv (smem-staged, coalesced; atomicAdd
// performs the reduction over the 8 ky-warps AND the 8 cc-blocks).
// Block = (cc in 0..7 [32-channel slice], fyh in 0..1, n). 256 threads =
// (ky 0..7) x (cl 0..31). W slice + one fy patch band staged in smem.
// ---------------------------------------------------------------------------
#define WS 68                      // padded W row stride (floats)
#define PS 516                     // padded patch per-channel stride (floats)
#define CONV_SMEM ((9*32*WS + 32*PS) * 4)

__global__ __launch_bounds__(256, 1)
void conv_kernel(const float* __restrict__ feat, const float* __restrict__ Wreg) {
    extern __shared__ float sm[];
    float* Wsl   = sm;               // [9][32][WS]
    float* patch = sm + 9*32*WS;     // [32][PS] (8 rows x 64 cols used)
    int cc  = blockIdx.x;
    int fyh = blockIdx.y;
    int n   = blockIdx.z;
    int tid = threadIdx.x;
    int ky = tid >> 5, cl = tid & 31;

    // Stage W slice: 9 * 32 * 64 floats, coalesced float4 loads
    #pragma unroll
    for (int it = 0; it < 18; it++) {
        int idx4 = it*256 + tid;       // 0..4607 float4s
        int aa  = idx4 >> 9;
        int rem = idx4 & 511;
        int clw = rem >> 4;
        int p4  = rem & 15;
        float4 v = *(const float4*)(Wreg + ((size_t)(aa*256 + cc*32 + clw)*64 + p4*4));
        *(float4*)(Wsl + (aa*32 + clw)*WS + p4*4) = v;
    }
    __syncthreads();

    for (int fy = fyh*4; fy < fyh*4 + 4; fy++) {
        // Stage patch band: 32c x 8 rows x 64 cols, coalesced float4
        #pragma unroll
        for (int it = 0; it < 16; it++) {
            int idx4 = it*256 + tid;   // 0..4095
            int clp = idx4 >> 7;
            int rem = idx4 & 127;
            int kyp = rem >> 4;
            int x4  = rem & 15;
            float4 v = *(const float4*)(feat +
                (((size_t)(n*256 + cc*32 + clp)*64 + fy*8 + kyp)*64 + x4*4));
            *(float4*)(patch + clp*PS + kyp*64 + x4*4) = v;
        }
        __syncthreads();

        // Each thread owns (cl, ky): its 64-pixel row band in registers
        float px[64];
        #pragma unroll
        for (int x4 = 0; x4 < 16; x4++) {
            float4 v = *(const float4*)(patch + cl*PS + ky*64 + x4*4);
            px[x4*4+0] = v.x; px[x4*4+1] = v.y; px[x4*4+2] = v.z; px[x4*4+3] = v.w;
        }
        #pragma unroll
        for (int aa = 0; aa < 9; aa++) {
            float w[8];
            float4 v0 = *(const float4*)(Wsl + (aa*32 + cl)*WS + ky*8);
            float4 v1 = *(const float4*)(Wsl + (aa*32 + cl)*WS + ky*8 + 4);
            w[0]=v0.x; w[1]=v0.y; w[2]=v0.z; w[3]=v0.w;
            w[4]=v1.x; w[5]=v1.y; w[6]=v1.z; w[7]=v1.w;
            #pragma unroll
            for (int fx = 0; fx < 8; fx++) {
                float acc = 0.f;
                #pragma unroll
                for (int kx = 0; kx < 8; kx++)
                    acc = fmaf(px[fx*8 + kx], w[kx], acc);
                #pragma unroll
                for (int off = 16; off; off >>= 1)
                    acc += __shfl_down_sync(0xffffffffu, acc, off);
                if (cl == 0)
                    atomicAdd(&g_reg[((n*9 + aa)*8 + fy)*8 + fx], acc);
            }
        }
        __syncthreads();
    }
}

// ---------------------------------------------------------------------------
// Kernel 3: tanh offset + bilinear sample DIRECTLY from NCHW feature.
// Feature is L2-resident (33MB); gathers hit mostly-shared sectors
// (x0,x0+1 adjacent). No clamps needed: px,py in [2.7, 60.3] always.
// Block = (k, n, aa-triple). Thread = c.
// ---------------------------------------------------------------------------
__global__ __launch_bounds__(256)
void sample_kernel(const float* __restrict__ feat, const float* __restrict__ breg) {
    int k = blockIdx.x;
    int n = blockIdx.y;
    int fy = k >> 3, fx = k & 7;
    int c = threadIdx.x;
    const float* fc = feat + ((size_t)(n*256 + c)) * 4096;
    #pragma unroll
    for (int ai = 0; ai < 3; ai++) {
        int aa = blockIdx.z * 3 + ai;
        float rg = g_reg[((n*9 + aa)*8 + fy)*8 + fx] + breg[aa];
        float d  = 0.8f * tanhf(rg);
        float pxx = 3.5f + 8.f*fx + d;
        float pyy = 3.5f + 8.f*fy + d;
        float x0f = floorf(pxx), y0f = floorf(pyy);
        float wx = pxx - x0f, wy = pyy - y0f;
        int x0 = (int)x0f;          // in [2,60] — no clamping possible
        int y0 = (int)y0f;
        const float* p0 = fc + y0*64 + x0;
        float v00 = p0[0];
        float v01 = p0[1];
        float v10 = p0[64];
        float v11 = p0[65];
        float val = v00*(1.f-wx)*(1.f-wy) + v01*wx*(1.f-wy)
                  + v10*(1.f-wx)*wy       + v11*wx*wy;
        g_roisb[((size_t)(aa*8 + n)*64 + k)*256 + c] = val;
    }
}

// ---------------------------------------------------------------------------
// Kernel 4: rois_to_rois with f16x2 EX2; f16->f32 unpack done with integer
// ops (bits = h16*8192 + 0x38000000) on ALU/FMA pipes, avoiding the
// quarter-rate cvt pipe. Subnormal/zero f16 inputs (h16 < 0x0400, i.e.
// p < -14) are flushed to exactly 0 via a select — their true contribution
// is < 6e-5 of the max term. p computed in f32 (FMA2) for exact
// max-cancellation.
// out_j = b_j + (sum_i a_i 2^{p_i})/(sum_i 2^{p_i}) * ln2, p_i = a'_i b_j - m'
// ---------------------------------------------------------------------------
__global__ __launch_bounds__(256, 2)
void roisB_kernel(const float* __restrict__ Ain, const float* __restrict__ Bin,
                  float* __restrict__ Out) {
    int g  = blockIdx.y;   // aa*8 + n
    int jq = blockIdx.x;   // quarter of j
    int c  = threadIdx.x;
    const float* Ab = Ain + (size_t)g*64*256 + c;
    const float* Bb = Bin + (size_t)g*64*256 + c;
    float*       Ob = Out + (size_t)g*64*256 + c;

    float bjv[16];
    #pragma unroll
    for (int jj = 0; jj < 16; jj++)
        bjv[jj] = Bb[(jq*16 + jj)*256];

    unsigned long long ap2[32];
    float amax = -1e30f, amin = 1e30f;
    #pragma unroll
    for (int k = 0; k < 32; k++) {
        float v0 = Ab[(2*k  )*256] * 1.4426950408889634f;
        float v1 = Ab[(2*k+1)*256] * 1.4426950408889634f;
        amax = fmaxf(amax, fmaxf(v0, v1));
        amin = fminf(amin, fminf(v0, v1));
        ap2[k] = ((unsigned long long)__float_as_uint(v1) << 32)
               |  (unsigned long long)__float_as_uint(v0);
    }

    #pragma unroll 1
    for (int jj = 0; jj < 16; jj++) {
        float bj  = bjv[jj];
        float mm  = fmaxf(bj*amax, bj*amin);   // exact max_i a'_i*bj
        float nmm = -mm;
        unsigned long long bj2 = ((unsigned long long)__float_as_uint(bj)  << 32)
                               |  (unsigned long long)__float_as_uint(bj);
        unsigned long long nm2 = ((unsigned long long)__float_as_uint(nmm) << 32)
                               |  (unsigned long long)__float_as_uint(nmm);
        unsigned long long s2 = 0ull, t2 = 0ull;   // packed f32x2 {0,0}
        #pragma unroll
        for (int i = 0; i < 32; i++) {
            unsigned long long p2, e2;
            unsigned int eh;
            asm("fma.rn.f32x2 %0, %1, %2, %3;"
                : "=l"(p2) : "l"(ap2[i]), "l"(bj2), "l"(nm2));
            asm("{\n\t.reg .b32 lo, hi;\n\t"
                "mov.b64 {lo, hi}, %1;\n\t"
                "cvt.rn.f16x2.f32 %0, hi, lo;\n\t}"
                : "=r"(eh) : "l"(p2));
            asm("ex2.approx.f16x2 %0, %0;" : "+r"(eh));
            // integer f16 -> f32 bit conversion (exact for normal f16);
            // subnormal/zero halves (h < 0x0400) flushed to exactly 0.
            unsigned int hlo = eh & 0xFFFFu;
            unsigned int hhi = eh >> 16;
            unsigned int lo_b = (hlo >= 0x0400u) ? (hlo * 8192u + 0x38000000u) : 0u;
            unsigned int hi_b = (hhi >= 0x0400u) ? (hhi * 8192u + 0x38000000u) : 0u;
            asm("mov.b64 %0, {%1, %2};" : "=l"(e2) : "r"(lo_b), "r"(hi_b));
            asm("add.rn.f32x2 %0, %0, %1;" : "+l"(s2) : "l"(e2));
            asm("fma.rn.f32x2 %0, %1, %2, %0;" : "+l"(t2) : "l"(ap2[i]), "l"(e2));
        }
        float s = __uint_as_float((unsigned)s2) + __uint_as_float((unsigned)(s2 >> 32));
        float t = __uint_as_float((unsigned)t2) + __uint_as_float((unsigned)(t2 >> 32));
        Ob[(jq*16 + jj)*256] = bj + __fdividef(t * 0.6931471805599453f, s);
    }
}

// ---------------------------------------------------------------------------
// Launch sequence (default stream, graph-capturable; no sync, no alloc)
// ---------------------------------------------------------------------------
extern "C" void kernel_launch(void* const* d_in, const int* in_sizes, int n_in,
                              void* d_out, int out_size) {
    const float* rois_a = (const float*)d_in[1];
    const float* feat   = (const float*)d_in[2];
    const float* rois_c = (const float*)d_in[3];
    const float* Wreg   = (const float*)d_in[4];
    const float* breg   = (const float*)d_in[5];
    float* out = (float*)d_out;

    cudaFuncSetAttribute(conv_kernel,
                         cudaFuncAttributeMaxDynamicSharedMemorySize, CONV_SMEM);

    void *p_roisb = nullptr, *p_tmp = nullptr;
    cudaGetSymbolAddress(&p_roisb, g_roisb);
    cudaGetSymbolAddress(&p_tmp, g_tmp);

    zero_reg_kernel<<<18, 256>>>();
    conv_kernel<<<dim3(8, 2, 8), 256, CONV_SMEM>>>(feat, Wreg);
    sample_kernel<<<dim3(64, 8, 3), 256>>>(feat, breg);
    roisB_kernel<<<dim3(4, 72), 256>>>(rois_a, (const float*)p_roisb, (float*)p_tmp);
    roisB_kernel<<<dim3(4, 72), 256>>>((const float*)p_tmp, rois_c, out);
}

// round 14
// speedup vs baseline: 1.4058x; 1.4058x over previous
#include <cuda_runtime.h>
#include <cstdint>
#include <cstddef>

// Problem constants (fixed by setup_inputs)
#define N_ 8
#define C_ 256
#define H_ 64
#define W_ 64
#define A_ 9
#define BS_ 8
#define F_ 8
#define K_ 64
#define M_ (A_*N_*K_)   // 4608

// Scratch (static device globals; no runtime allocation)
__device__ float g_reg[N_*A_*F_*F_];           // 4608 conv outputs
__device__ float g_roisb[(size_t)M_*C_];       // sampled rois_feature_b
__device__ float g_tmp[(size_t)M_*C_];         // intermediate rois output

// ---------------------------------------------------------------------------
// Kernel 1: zero the conv accumulator (atomics accumulate into it each launch)
// ---------------------------------------------------------------------------
__global__ void zero_reg_kernel() {
    int i = blockIdx.x * blockDim.x + threadIdx.x;
    if (i < N_*A_*F_*F_) g_reg[i] = 0.f;
}

// ---------------------------------------------------------------------------
// Kernel 2: stride-8 8x8 "VALID" conv (smem-staged, coalesced; atomicAdd
// performs the reduction over the 8 ky-warps AND the 8 cc-blocks).
// Block = (cc in 0..7 [32-channel slice], fyh in 0..1, n). 256 threads =
// (ky 0..7) x (cl 0..31). W slice + one fy patch band staged in smem.
// ---------------------------------------------------------------------------
#define WS 68                      // padded W row stride (floats)
#define PS 516                     // padded patch per-channel stride (floats)
#define CONV_SMEM ((9*32*WS + 32*PS) * 4)

__global__ __launch_bounds__(256, 1)
void conv_kernel(const float* __restrict__ feat, const float* __restrict__ Wreg) {
    extern __shared__ float sm[];
    float* Wsl   = sm;               // [9][32][WS]
    float* patch = sm + 9*32*WS;     // [32][PS] (8 rows x 64 cols used)
    int cc  = blockIdx.x;
    int fyh = blockIdx.y;
    int n   = blockIdx.z;
    int tid = threadIdx.x;
    int ky = tid >> 5, cl = tid & 31;

    // Stage W slice: 9 * 32 * 64 floats, coalesced float4 loads
    #pragma unroll
    for (int it = 0; it < 18; it++) {
        int idx4 = it*256 + tid;       // 0..4607 float4s
        int aa  = idx4 >> 9;
        int rem = idx4 & 511;
        int clw = rem >> 4;
        int p4  = rem & 15;
        float4 v = *(const float4*)(Wreg + ((size_t)(aa*256 + cc*32 + clw)*64 + p4*4));
        *(float4*)(Wsl + (aa*32 + clw)*WS + p4*4) = v;
    }
    __syncthreads();

    for (int fy = fyh*4; fy < fyh*4 + 4; fy++) {
        // Stage patch band: 32c x 8 rows x 64 cols, coalesced float4
        #pragma unroll
        for (int it = 0; it < 16; it++) {
            int idx4 = it*256 + tid;   // 0..4095
            int clp = idx4 >> 7;
            int rem = idx4 & 127;
            int kyp = rem >> 4;
            int x4  = rem & 15;
            float4 v = *(const float4*)(feat +
                (((size_t)(n*256 + cc*32 + clp)*64 + fy*8 + kyp)*64 + x4*4));
            *(float4*)(patch + clp*PS + kyp*64 + x4*4) = v;
        }
        __syncthreads();

        // Each thread owns (cl, ky): its 64-pixel row band in registers
        float px[64];
        #pragma unroll
        for (int x4 = 0; x4 < 16; x4++) {
            float4 v = *(const float4*)(patch + cl*PS + ky*64 + x4*4);
            px[x4*4+0] = v.x; px[x4*4+1] = v.y; px[x4*4+2] = v.z; px[x4*4+3] = v.w;
        }
        #pragma unroll
        for (int aa = 0; aa < 9; aa++) {
            float w[8];
            float4 v0 = *(const float4*)(Wsl + (aa*32 + cl)*WS + ky*8);
            float4 v1 = *(const float4*)(Wsl + (aa*32 + cl)*WS + ky*8 + 4);
            w[0]=v0.x; w[1]=v0.y; w[2]=v0.z; w[3]=v0.w;
            w[4]=v1.x; w[5]=v1.y; w[6]=v1.z; w[7]=v1.w;
            #pragma unroll
            for (int fx = 0; fx < 8; fx++) {
                float acc = 0.f;
                #pragma unroll
                for (int kx = 0; kx < 8; kx++)
                    acc = fmaf(px[fx*8 + kx], w[kx], acc);
                #pragma unroll
                for (int off = 16; off; off >>= 1)
                    acc += __shfl_down_sync(0xffffffffu, acc, off);
                if (cl == 0)
                    atomicAdd(&g_reg[((n*9 + aa)*8 + fy)*8 + fx], acc);
            }
        }
        __syncthreads();
    }
}

// ---------------------------------------------------------------------------
// Kernel 3: window sample — transpose-free bilinear sampling.
// KEY FACT: |d| = |0.8*tanh| < 0.8, so for tile (fy,fx) ALL 9 anchors' taps
// lie in the fixed 4x4 pixel window x in [8fx+2, 8fx+5], y in [8fy+2, 8fy+5].
// Block = (k, n). Each thread (c) stages its 4x4 window pixels into smem
// (each pixel read ONCE from NCHW), then computes all 9 aa outputs from
// conflict-free LDS and writes g_roisb coalesced.
// smem layout: sw[y][x][c] = [4][4][256] floats = 16KB.
// ---------------------------------------------------------------------------
__global__ __launch_bounds__(256)
void wsample_kernel(const float* __restrict__ feat, const float* __restrict__ breg) {
    __shared__ float sw[4][4][256];
    __shared__ float sd[9];          // per-anchor offset d (same for all c)
    int k = blockIdx.x;
    int n = blockIdx.y;
    int fy = k >> 3, fx = k & 7;
    int c = threadIdx.x;
    int xb = 8*fx + 2, yb = 8*fy + 2;

    // Stage 4x4 window for this thread's channel: 4 rows x 2 float2 loads
    const float* fc = feat + ((size_t)(n*256 + c)) * 4096;
    #pragma unroll
    for (int y = 0; y < 4; y++) {
        const float* rp = fc + (yb + y)*64 + xb;   // 8B-aligned (xb even)
        float2 a = *(const float2*)rp;
        float2 b = *(const float2*)(rp + 2);
        sw[y][0][c] = a.x; sw[y][1][c] = a.y;
        sw[y][2][c] = b.x; sw[y][3][c] = b.y;
    }
    // First 9 threads compute the per-anchor offsets (one tanh each)
    if (c < 9) {
        float rg = g_reg[((n*9 + c)*8 + fy)*8 + fx] + breg[c];
        sd[c] = 0.8f * tanhf(rg);
    }
    __syncthreads();

    #pragma unroll
    for (int aa = 0; aa < 9; aa++) {
        float d  = sd[aa];
        float pxx = 3.5f + 8.f*fx + d;
        float pyy = 3.5f + 8.f*fy + d;
        float x0f = floorf(pxx), y0f = floorf(pyy);
        float wx = pxx - x0f, wy = pyy - y0f;
        int x0l = (int)x0f - xb;     // in {0,1,2}
        int y0l = (int)y0f - yb;     // in {0,1,2}
        float v00 = sw[y0l  ][x0l  ][c];
        float v01 = sw[y0l  ][x0l+1][c];
        float v10 = sw[y0l+1][x0l  ][c];
        float v11 = sw[y0l+1][x0l+1][c];
        float val = v00*(1.f-wx)*(1.f-wy) + v01*wx*(1.f-wy)
                  + v10*(1.f-wx)*wy       + v11*wx*wy;
        g_roisb[((size_t)(aa*8 + n)*64 + k)*256 + c] = val;
    }
}

// ---------------------------------------------------------------------------
// Kernel 4: rois_to_rois with f16x2 EX2 + packed f32x2 accumulation (exact
// R4 version: cvt-based unpack handles subnormals correctly; F2FP pack is a
// cheap fixed-pipe op, only the two F2F unpacks ride XU).
// out_j = b_j + (sum_i a_i 2^{p_i})/(sum_i 2^{p_i}) * ln2, p_i = a'_i b_j - m'
// a' = a*log2(e); m' = max(b_j a'max, b_j a'min) folds exact max into FMA2.
// ---------------------------------------------------------------------------
__global__ __launch_bounds__(256, 2)
void roisB_kernel(const float* __restrict__ Ain, const float* __restrict__ Bin,
                  float* __restrict__ Out) {
    int g  = blockIdx.y;   // aa*8 + n
    int jq = blockIdx.x;   // quarter of j
    int c  = threadIdx.x;
    const float* Ab = Ain + (size_t)g*64*256 + c;
    const float* Bb = Bin + (size_t)g*64*256 + c;
    float*       Ob = Out + (size_t)g*64*256 + c;

    float bjv[16];
    #pragma unroll
    for (int jj = 0; jj < 16; jj++)
        bjv[jj] = Bb[(jq*16 + jj)*256];

    unsigned long long ap2[32];
    float amax = -1e30f, amin = 1e30f;
    #pragma unroll
    for (int k = 0; k < 32; k++) {
        float v0 = Ab[(2*k  )*256] * 1.4426950408889634f;
        float v1 = Ab[(2*k+1)*256] * 1.4426950408889634f;
        amax = fmaxf(amax, fmaxf(v0, v1));
        amin = fminf(amin, fminf(v0, v1));
        ap2[k] = ((unsigned long long)__float_as_uint(v1) << 32)
               |  (unsigned long long)__float_as_uint(v0);
    }

    #pragma unroll 1
    for (int jj = 0; jj < 16; jj++) {
        float bj  = bjv[jj];
        float mm  = fmaxf(bj*amax, bj*amin);   // exact max_i a'_i*bj
        float nmm = -mm;
        unsigned long long bj2 = ((unsigned long long)__float_as_uint(bj)  << 32)
                               |  (unsigned long long)__float_as_uint(bj);
        unsigned long long nm2 = ((unsigned long long)__float_as_uint(nmm) << 32)
                               |  (unsigned long long)__float_as_uint(nmm);
        unsigned long long s2 = 0ull, t2 = 0ull;   // packed f32x2 {0,0}
        #pragma unroll
        for (int i = 0; i < 32; i++) {
            unsigned long long p2, e2;
            unsigned int eh;
            asm("fma.rn.f32x2 %0, %1, %2, %3;"
                : "=l"(p2) : "l"(ap2[i]), "l"(bj2), "l"(nm2));
            asm("{\n\t.reg .b32 lo, hi;\n\t"
                "mov.b64 {lo, hi}, %1;\n\t"
                "cvt.rn.f16x2.f32 %0, hi, lo;\n\t}"
                : "=r"(eh) : "l"(p2));
            asm("ex2.approx.f16x2 %0, %0;" : "+r"(eh));
            asm("{\n\t.reg .f16 l16, h16;\n\t.reg .f32 lf, hf;\n\t"
                "mov.b32 {l16, h16}, %1;\n\t"
                "cvt.f32.f16 lf, l16;\n\t"
                "cvt.f32.f16 hf, h16;\n\t"
                "mov.b64 %0, {lf, hf};\n\t}"
                : "=l"(e2) : "r"(eh));
            asm("add.rn.f32x2 %0, %0, %1;" : "+l"(s2) : "l"(e2));
            asm("fma.rn.f32x2 %0, %1, %2, %0;" : "+l"(t2) : "l"(ap2[i]), "l"(e2));
        }
        float s = __uint_as_float((unsigned)s2) + __uint_as_float((unsigned)(s2 >> 32));
        float t = __uint_as_float((unsigned)t2) + __uint_as_float((unsigned)(t2 >> 32));
        Ob[(jq*16 + jj)*256] = bj + __fdividef(t * 0.6931471805599453f, s);
    }
}

// ---------------------------------------------------------------------------
// Launch sequence (default stream, graph-capturable; no sync, no alloc)
// ---------------------------------------------------------------------------
extern "C" void kernel_launch(void* const* d_in, const int* in_sizes, int n_in,
                              void* d_out, int out_size) {
    const float* rois_a = (const float*)d_in[1];
    const float* feat   = (const float*)d_in[2];
    const float* rois_c = (const float*)d_in[3];
    const float* Wreg   = (const float*)d_in[4];
    const float* breg   = (const float*)d_in[5];
    float* out = (float*)d_out;

    cudaFuncSetAttribute(conv_kernel,
                         cudaFuncAttributeMaxDynamicSharedMemorySize, CONV_SMEM);

    void *p_roisb = nullptr, *p_tmp = nullptr;
    cudaGetSymbolAddress(&p_roisb, g_roisb);
    cudaGetSymbolAddress(&p_tmp, g_tmp);

    zero_reg_kernel<<<18, 256>>>();
    conv_kernel<<<dim3(8, 2, 8), 256, CONV_SMEM>>>(feat, Wreg);
    wsample_kernel<<<dim3(64, 8), 256>>>(feat, breg);
    roisB_kernel<<<dim3(4, 72), 256>>>(rois_a, (const float*)p_roisb, (float*)p_tmp);
    roisB_kernel<<<dim3(4, 72), 256>>>((const float*)p_tmp, rois_c, out);
}

// round 16
// speedup vs baseline: 1.6297x; 1.1593x over previous
#include <cuda_runtime.h>
#include <cstdint>
#include <cstddef>

// Problem constants (fixed by setup_inputs)
#define N_ 8
#define C_ 256
#define H_ 64
#define W_ 64
#define A_ 9
#define BS_ 8
#define F_ 8
#define K_ 64
#define M_ (A_*N_*K_)   // 4608

// Scratch (static device globals; no runtime allocation)
__device__ float g_regp[8][N_*A_*F_*F_];       // conv partials (8 c-slices)
__device__ float g_roisb[(size_t)M_*C_];       // sampled rois_feature_b
__device__ float g_tmp[(size_t)M_*C_];         // intermediate rois output

// ---------------------------------------------------------------------------
// Kernel 1: stride-8 8x8 "VALID" conv (smem-staged, coalesced), atomic-free.
// Block = (cc in 0..7 [32-channel slice], fyh in 0..1, n). 256 threads =
// (ky 0..7) x (cl 0..31). Per (aa,fx): shfl-reduce over cl lanes, lane0 of
// each ky-warp writes smem red[ky][aa*8+fx]; after sync, threads 0..71 sum
// the 8 ky partials and plain-store to g_regp[cc] (blocks sharing cc write
// DISJOINT (n,fy) ranges — no race). wsample sums the 8 cc partials.
// ---------------------------------------------------------------------------
#define WS 68                      // padded W row stride (floats)
#define PS 516                     // padded patch per-channel stride (floats)
#define CONV_SMEM ((9*32*WS + 32*PS) * 4)

__global__ __launch_bounds__(256, 1)
void conv_kernel(const float* __restrict__ feat, const float* __restrict__ Wreg) {
    extern __shared__ float sm[];
    __shared__ float red[8][72];     // [ky][aa*8+fx]
    float* Wsl   = sm;               // [9][32][WS]
    float* patch = sm + 9*32*WS;     // [32][PS] (8 rows x 64 cols used)
    int cc  = blockIdx.x;
    int fyh = blockIdx.y;
    int n   = blockIdx.z;
    int tid = threadIdx.x;
    int ky = tid >> 5, cl = tid & 31;

    // Stage W slice: 9 * 32 * 64 floats, coalesced float4 loads
    #pragma unroll
    for (int it = 0; it < 18; it++) {
        int idx4 = it*256 + tid;       // 0..4607 float4s
        int aa  = idx4 >> 9;
        int rem = idx4 & 511;
        int clw = rem >> 4;
        int p4  = rem & 15;
        float4 v = *(const float4*)(Wreg + ((size_t)(aa*256 + cc*32 + clw)*64 + p4*4));
        *(float4*)(Wsl + (aa*32 + clw)*WS + p4*4) = v;
    }
    __syncthreads();

    for (int fy = fyh*4; fy < fyh*4 + 4; fy++) {
        // Stage patch band: 32c x 8 rows x 64 cols, coalesced float4
        #pragma unroll
        for (int it = 0; it < 16; it++) {
            int idx4 = it*256 + tid;   // 0..4095
            int clp = idx4 >> 7;
            int rem = idx4 & 127;
            int kyp = rem >> 4;
            int x4  = rem & 15;
            float4 v = *(const float4*)(feat +
                (((size_t)(n*256 + cc*32 + clp)*64 + fy*8 + kyp)*64 + x4*4));
            *(float4*)(patch + clp*PS + kyp*64 + x4*4) = v;
        }
        __syncthreads();

        // Each thread owns (cl, ky): its 64-pixel row band in registers
        float px[64];
        #pragma unroll
        for (int x4 = 0; x4 < 16; x4++) {
            float4 v = *(const float4*)(patch + cl*PS + ky*64 + x4*4);
            px[x4*4+0] = v.x; px[x4*4+1] = v.y; px[x4*4+2] = v.z; px[x4*4+3] = v.w;
        }
        #pragma unroll
        for (int aa = 0; aa < 9; aa++) {
            float w[8];
            float4 v0 = *(const float4*)(Wsl + (aa*32 + cl)*WS + ky*8);
            float4 v1 = *(const float4*)(Wsl + (aa*32 + cl)*WS + ky*8 + 4);
            w[0]=v0.x; w[1]=v0.y; w[2]=v0.z; w[3]=v0.w;
            w[4]=v1.x; w[5]=v1.y; w[6]=v1.z; w[7]=v1.w;
            #pragma unroll
            for (int fx = 0; fx < 8; fx++) {
                float acc = 0.f;
                #pragma unroll
                for (int kx = 0; kx < 8; kx++)
                    acc = fmaf(px[fx*8 + kx], w[kx], acc);
                #pragma unroll
                for (int off = 16; off; off >>= 1)
                    acc += __shfl_down_sync(0xffffffffu, acc, off);
                if (cl == 0)
                    red[ky][aa*8 + fx] = acc;
            }
        }
        __syncthreads();   // red[] complete for this fy
        if (tid < 72) {
            float s = red[0][tid] + red[1][tid] + red[2][tid] + red[3][tid]
                    + red[4][tid] + red[5][tid] + red[6][tid] + red[7][tid];
            int aa = tid >> 3, fx = tid & 7;
            g_regp[cc][((n*9 + aa)*8 + fy)*8 + fx] = s;
        }
        __syncthreads();   // red[] free before next fy reuses it
    }
}

// ---------------------------------------------------------------------------
// Kernel 2: window sample — transpose-free bilinear sampling.
// |d| = |0.8*tanh| < 0.8, so for tile (fy,fx) ALL 9 anchors' taps lie in the
// fixed 4x4 window x in [8fx+2, 8fx+5], y in [8fy+2, 8fy+5].
// Block = (k, n). Thread c stages its 4x4 window into smem (each pixel read
// once), sums the 8 conv partials inline, computes all 9 aa outputs.
// ---------------------------------------------------------------------------
__global__ __launch_bounds__(256)
void wsample_kernel(const float* __restrict__ feat, const float* __restrict__ breg) {
    __shared__ float sw[4][4][256];
    __shared__ float sd[9];          // per-anchor offset d (same for all c)
    int k = blockIdx.x;
    int n = blockIdx.y;
    int fy = k >> 3, fx = k & 7;
    int c = threadIdx.x;
    int xb = 8*fx + 2, yb = 8*fy + 2;

    // Stage 4x4 window for this thread's channel: 4 rows x 2 float2 loads
    const float* fc = feat + ((size_t)(n*256 + c)) * 4096;
    #pragma unroll
    for (int y = 0; y < 4; y++) {
        const float* rp = fc + (yb + y)*64 + xb;   // 8B-aligned (xb even)
        float2 a = *(const float2*)rp;
        float2 b = *(const float2*)(rp + 2);
        sw[y][0][c] = a.x; sw[y][1][c] = a.y;
        sw[y][2][c] = b.x; sw[y][3][c] = b.y;
    }
    // First 9 threads compute the per-anchor offsets (one tanh each),
    // summing the 8 channel-slice conv partials.
    if (c < 9) {
        int ridx = ((n*9 + c)*8 + fy)*8 + fx;
        float rg = breg[c];
        #pragma unroll
        for (int cc = 0; cc < 8; cc++)
            rg += g_regp[cc][ridx];
        sd[c] = 0.8f * tanhf(rg);
    }
    __syncthreads();

    #pragma unroll
    for (int aa = 0; aa < 9; aa++) {
        float d  = sd[aa];
        float pxx = 3.5f + 8.f*fx + d;
        float pyy = 3.5f + 8.f*fy + d;
        float x0f = floorf(pxx), y0f = floorf(pyy);
        float wx = pxx - x0f, wy = pyy - y0f;
        int x0l = (int)x0f - xb;     // in {0,1,2}
        int y0l = (int)y0f - yb;     // in {0,1,2}
        float v00 = sw[y0l  ][x0l  ][c];
        float v01 = sw[y0l  ][x0l+1][c];
        float v10 = sw[y0l+1][x0l  ][c];
        float v11 = sw[y0l+1][x0l+1][c];
        float val = v00*(1.f-wx)*(1.f-wy) + v01*wx*(1.f-wy)
                  + v10*(1.f-wx)*wy       + v11*wx*wy;
        g_roisb[((size_t)(aa*8 + n)*64 + k)*256 + c] = val;
    }
}

// ---------------------------------------------------------------------------
// Kernel 3: rois_to_rois with f16x2 EX2, HYBRID unpack: high half via
// cvt.f32.f16 (XU pipe), low half via guarded integer bit-conversion
// (ALU pipe: bits = h*8192 + 0x38000000, exact for normal f16; subnormal
// flushed to 0). XU per pair drops 20 -> 16 cyc while ALU stays under the
// XU bound. Accumulation in packed f32x2.
// out_j = b_j + (sum_i a_i 2^{p_i})/(sum_i 2^{p_i}) * ln2, p_i = a'_i b_j - m'
// ---------------------------------------------------------------------------
__global__ __launch_bounds__(256, 2)
void roisB_kernel(const float* __restrict__ Ain, const float* __restrict__ Bin,
                  float* __restrict__ Out) {
    int g  = blockIdx.y;   // aa*8 + n
    int jq = blockIdx.x;   // quarter of j
    int c  = threadIdx.x;
    const float* Ab = Ain + (size_t)g*64*256 + c;
    const float* Bb = Bin + (size_t)g*64*256 + c;
    float*       Ob = Out + (size_t)g*64*256 + c;

    float bjv[16];
    #pragma unroll
    for (int jj = 0; jj < 16; jj++)
        bjv[jj] = Bb[(jq*16 + jj)*256];

    unsigned long long ap2[32];
    float amax = -1e30f, amin = 1e30f;
    #pragma unroll
    for (int k = 0; k < 32; k++) {
        float v0 = Ab[(2*k  )*256] * 1.4426950408889634f;
        float v1 = Ab[(2*k+1)*256] * 1.4426950408889634f;
        amax = fmaxf(amax, fmaxf(v0, v1));
        amin = fminf(amin, fminf(v0, v1));
        ap2[k] = ((unsigned long long)__float_as_uint(v1) << 32)
               |  (unsigned long long)__float_as_uint(v0);
    }

    #pragma unroll 1
    for (int jj = 0; jj < 16; jj++) {
        float bj  = bjv[jj];
        float mm  = fmaxf(bj*amax, bj*amin);   // exact max_i a'_i*bj
        float nmm = -mm;
        unsigned long long bj2 = ((unsigned long long)__float_as_uint(bj)  << 32)
                               |  (unsigned long long)__float_as_uint(bj);
        unsigned long long nm2 = ((unsigned long long)__float_as_uint(nmm) << 32)
                               |  (unsigned long long)__float_as_uint(nmm);
        unsigned long long s2 = 0ull, t2 = 0ull;   // packed f32x2 {0,0}
        #pragma unroll
        for (int i = 0; i < 32; i++) {
            unsigned long long p2, e2;
            unsigned int eh;
            asm("fma.rn.f32x2 %0, %1, %2, %3;"
                : "=l"(p2) : "l"(ap2[i]), "l"(bj2), "l"(nm2));
            asm("{\n\t.reg .b32 lo, hi;\n\t"
                "mov.b64 {lo, hi}, %1;\n\t"
                "cvt.rn.f16x2.f32 %0, hi, lo;\n\t}"
                : "=r"(eh) : "l"(p2));
            asm("ex2.approx.f16x2 %0, %0;" : "+r"(eh));
            // low half: integer f16->f32 (ALU pipe); guard flushes subnormals
            unsigned int hlo = eh & 0xFFFFu;
            unsigned int lo_b = (hlo >= 0x0400u) ? (hlo * 8192u + 0x38000000u) : 0u;
            float lo_f = __uint_as_float(lo_b);
            // high half: cvt (XU pipe); pack {lo_f, hi_f} into f32x2
            asm("{\n\t.reg .f16 l16, h16;\n\t.reg .f32 hf;\n\t"
                "mov.b32 {l16, h16}, %1;\n\t"
                "cvt.f32.f16 hf, h16;\n\t"
                "mov.b64 %0, {%2, hf};\n\t}"
                : "=l"(e2) : "r"(eh), "f"(lo_f));
            asm("add.rn.f32x2 %0, %0, %1;" : "+l"(s2) : "l"(e2));
            asm("fma.rn.f32x2 %0, %1, %2, %0;" : "+l"(t2) : "l"(ap2[i]), "l"(e2));
        }
        float s = __uint_as_float((unsigned)s2) + __uint_as_float((unsigned)(s2 >> 32));
        float t = __uint_as_float((unsigned)t2) + __uint_as_float((unsigned)(t2 >> 32));
        Ob[(jq*16 + jj)*256] = bj + __fdividef(t * 0.6931471805599453f, s);
    }
}

// ---------------------------------------------------------------------------
// Launch sequence (default stream, graph-capturable; no sync, no alloc)
// ---------------------------------------------------------------------------
extern "C" void kernel_launch(void* const* d_in, const int* in_sizes, int n_in,
                              void* d_out, int out_size) {
    const float* rois_a = (const float*)d_in[1];
    const float* feat   = (const float*)d_in[2];
    const float* rois_c = (const float*)d_in[3];
    const float* Wreg   = (const float*)d_in[4];
    const float* breg   = (const float*)d_in[5];
    float* out = (float*)d_out;

    cudaFuncSetAttribute(conv_kernel,
                         cudaFuncAttributeMaxDynamicSharedMemorySize, CONV_SMEM);

    void *p_roisb = nullptr, *p_tmp = nullptr;
    cudaGetSymbolAddress(&p_roisb, g_roisb);
    cudaGetSymbolAddress(&p_tmp, g_tmp);

    conv_kernel<<<dim3(8, 2, 8), 256, CONV_SMEM>>>(feat, Wreg);
    wsample_kernel<<<dim3(64, 8), 256>>>(feat, breg);
    roisB_kernel<<<dim3(4, 72), 256>>>(rois_a, (const float*)p_roisb, (float*)p_tmp);
    roisB_kernel<<<dim3(4, 72), 256>>>((const float*)p_tmp, rois_c, out);
}